// round 9
// baseline (speedup 1.0000x reference)
#include <cuda_runtime.h>

#define NB 64
#define LQ 256
#define EE 64
#define HH 64

// Scratch (static __device__ — no allocations allowed)
__device__ float g_vt[NB * LQ * EE];    // vt[n][l][k] = values[k][l][n]   (4 MB)
__device__ float g_attn[NB * EE * EE];  // attn[n][a][b]                   (1 MB)

// ---------------------------------------------------------------------------
// K_front: merged launch.
//   blocks [0,128):   energy Q·K^T + softmax -> g_attn   (n, half)  [long pole first]
//   blocks [128,384): transpose values[k][l][n] -> vt[n][l][k]  (one per l)
// ---------------------------------------------------------------------------
__global__ void __launch_bounds__(256) k_front(const float* __restrict__ values,
                                               const float* __restrict__ query,
                                               const float* __restrict__ keys) {
    __shared__ float sh[5248];           // aliased pool (max of both phases)
    const int tid = threadIdx.x;

    if (blockIdx.x >= 128) {
        // ---- transpose phase ----
        float (*tile)[65] = (float(*)[65])sh;
        const int l = blockIdx.x - 128;
#pragma unroll
        for (int i = 0; i < 4; i++) {
            int f = i * 256 + tid;          // float4 index 0..1023
            int k = f >> 4;                 // 0..63
            int n4 = f & 15;                // 0..15
            float4 v = *(const float4*)(values + ((k * LQ + l) * EE) + n4 * 4);
            tile[k][n4 * 4 + 0] = v.x;
            tile[k][n4 * 4 + 1] = v.y;
            tile[k][n4 * 4 + 2] = v.z;
            tile[k][n4 * 4 + 3] = v.w;
        }
        __syncthreads();
#pragma unroll
        for (int i = 0; i < 4; i++) {
            int f = i * 256 + tid;
            int nn = f >> 4;
            int k4 = f & 15;
            float4 v = make_float4(tile[k4 * 4 + 0][nn], tile[k4 * 4 + 1][nn],
                                   tile[k4 * 4 + 2][nn], tile[k4 * 4 + 3][nn]);
            *(float4*)(g_vt + ((nn * LQ + l) * EE) + k4 * 4) = v;
        }
        return;
    }

    // ---- attention phase ----
    const int bb = blockIdx.x;
    const int n = bb >> 1;
    const int half = bb & 1;
    float (*sQ)[32] = (float(*)[32])sh;            // [l'][a_local]  1024
    float (*sK)[64] = (float(*)[64])(sh + 1024);   // [l'][b]        2048
    float (*sE)[68] = (float(*)[68])(sh + 3072);   // energy         2176
    const int a0 = (tid >> 4) * 2;  // 0..30 step 2
    const int b0 = (tid & 15) * 4;  // 0..60 step 4

    float a00 = 0.f, a01 = 0.f, a02 = 0.f, a03 = 0.f;
    float a10 = 0.f, a11 = 0.f, a12 = 0.f, a13 = 0.f;

    for (int l0 = 0; l0 < LQ; l0 += 32) {
        {
            int lp = tid >> 3;  // 0..31
            int q4 = tid & 7;   // 0..7
            float4 v = *(const float4*)(query + ((n * LQ + l0 + lp) * EE) + half * 32 + q4 * 4);
            *(float4*)&sQ[lp][q4 * 4] = v;
        }
#pragma unroll
        for (int j = 0; j < 2; j++) {
            int f = j * 256 + tid;
            int lp = f >> 4;
            int b4 = f & 15;
            float4 v = *(const float4*)(keys + ((n * LQ + l0 + lp) * EE) + b4 * 4);
            *(float4*)&sK[lp][b4 * 4] = v;
        }
        __syncthreads();
#pragma unroll
        for (int lp = 0; lp < 32; lp++) {
            float2 qv = *(const float2*)&sQ[lp][a0];
            float4 kv = *(const float4*)&sK[lp][b0];
            a00 += qv.x * kv.x; a01 += qv.x * kv.y; a02 += qv.x * kv.z; a03 += qv.x * kv.w;
            a10 += qv.y * kv.x; a11 += qv.y * kv.y; a12 += qv.y * kv.z; a13 += qv.y * kv.w;
        }
        __syncthreads();
    }
    *(float4*)&sE[a0][b0]     = make_float4(a00, a01, a02, a03);
    *(float4*)&sE[a0 + 1][b0] = make_float4(a10, a11, a12, a13);
    __syncthreads();

    // softmax: 8 warps x 4 rows each (32 rows in this half); hd=1 so no scale
    const int w = tid >> 5, lane = tid & 31;
#pragma unroll
    for (int r = 0; r < 4; r++) {
        int row = w * 4 + r;
        float v0 = sE[row][lane];
        float v1 = sE[row][lane + 32];
        float m = fmaxf(v0, v1);
#pragma unroll
        for (int off = 16; off; off >>= 1) m = fmaxf(m, __shfl_xor_sync(0xffffffffu, m, off));
        float e0 = __expf(v0 - m);
        float e1 = __expf(v1 - m);
        float s = e0 + e1;
#pragma unroll
        for (int off = 16; off; off >>= 1) s += __shfl_xor_sync(0xffffffffu, s, off);
        float inv = 1.0f / s;
        float* dst = g_attn + (n * EE + half * 32 + row) * EE;
        dst[lane] = e0 * inv;
        dst[lane + 32] = e1 * inv;
    }
}

// ---------------------------------------------------------------------------
// K3: fused  M_n = W @ A_n  +  GEMV + LayerNorm; writes ONLY the h=0 slice.
// grid: 512 blocks = (n, 32-l chunk); 256 threads.
// Each block recomputes its n's M (8x redundancy, ~1K FMA/thread) to avoid
// a separate poorly-occupied k_M launch + inter-kernel dependency.
// ---------------------------------------------------------------------------
__global__ void __launch_bounds__(256) k_compute(const float* __restrict__ W,
                                                 const float* __restrict__ bias,
                                                 const float* __restrict__ lnw,
                                                 const float* __restrict__ lnb,
                                                 float* __restrict__ out) {
    const int n = blockIdx.x >> 3;
    const int lc = blockIdx.x & 7;
    const int tid = threadIdx.x;

    __shared__ float sWt[64][68];   // sWt[e'][e] = W[e][e']       (17.4 KB)
    __shared__ float sA[64][68];    // sA[e'][k] = attn[n][e'][k]  (17.4 KB)
    __shared__ float sMt[64][68];   // sMt[k][e] = M_n[e][k]       (17.4 KB)
    __shared__ float sv[32][68];    // sv[l'][k]  vt tile          ( 8.7 KB)
    __shared__ float sy[32][64];    // normalized output tile      ( 8.0 KB)
    __shared__ float sb[64], sw[64], sbeta[64];

    if (tid < 64) {
        sb[tid] = bias[tid];
        sw[tid] = lnw[tid];
        sbeta[tid] = lnb[tid];
    }

    // ---- stage W^T and A_n ----
    const float* An = g_attn + n * 4096;
#pragma unroll
    for (int i = 0; i < 16; i++) {
        int idx = i * 256 + tid;
        int r = idx >> 6, c = idx & 63;
        sWt[c][r] = W[idx];            // transpose W on the fly
        sA[r][c] = An[idx];
    }
    // ---- load vt tile (32 x 64), coalesced ----
    const int lbase = lc * 32;
    const float* vtn = g_vt + (n * LQ + lbase) * EE;
#pragma unroll
    for (int i = 0; i < 8; i++) {
        int idx = i * 256 + tid;
        sv[idx >> 6][idx & 63] = vtn[idx];
    }
    __syncthreads();

    // ---- M_n[e][k] = sum_e' W[e][e'] * A_n[e'][k], stored transposed ----
    {
        const int e0 = (tid >> 4) * 4;
        const int k0 = (tid & 15) * 4;
        float acc[4][4] = {};
#pragma unroll
        for (int ep = 0; ep < 64; ep++) {
            float4 wv = *(const float4*)&sWt[ep][e0];
            float4 av = *(const float4*)&sA[ep][k0];
            acc[0][0] += wv.x * av.x; acc[0][1] += wv.x * av.y; acc[0][2] += wv.x * av.z; acc[0][3] += wv.x * av.w;
            acc[1][0] += wv.y * av.x; acc[1][1] += wv.y * av.y; acc[1][2] += wv.y * av.z; acc[1][3] += wv.y * av.w;
            acc[2][0] += wv.z * av.x; acc[2][1] += wv.z * av.y; acc[2][2] += wv.z * av.z; acc[2][3] += wv.z * av.w;
            acc[3][0] += wv.w * av.x; acc[3][1] += wv.w * av.y; acc[3][2] += wv.w * av.z; acc[3][3] += wv.w * av.w;
        }
#pragma unroll
        for (int i = 0; i < 4; i++)
#pragma unroll
            for (int j = 0; j < 4; j++)
                sMt[k0 + j][e0 + i] = acc[i][j];
    }
    __syncthreads();

    // ---- GEMV micro-tile: 2 l-rows x 4 e-cols per thread ----
    const int r0 = (tid >> 4) * 2;   // 0..30
    const int e0 = (tid & 15) * 4;   // 0..60

    float a00 = 0.f, a01 = 0.f, a02 = 0.f, a03 = 0.f;
    float a10 = 0.f, a11 = 0.f, a12 = 0.f, a13 = 0.f;
#pragma unroll
    for (int k = 0; k < 64; k++) {
        float v0 = sv[r0][k];
        float v1 = sv[r0 + 1][k];
        float4 m = *(const float4*)&sMt[k][e0];
        a00 += v0 * m.x; a01 += v0 * m.y; a02 += v0 * m.z; a03 += v0 * m.w;
        a10 += v1 * m.x; a11 += v1 * m.y; a12 += v1 * m.z; a13 += v1 * m.w;
    }
    // add fc bias before LN
    float b0v = sb[e0], b1v = sb[e0 + 1], b2v = sb[e0 + 2], b3v = sb[e0 + 3];
    a00 += b0v; a01 += b1v; a02 += b2v; a03 += b3v;
    a10 += b0v; a11 += b1v; a12 += b2v; a13 += b3v;

    // LN stats: reduce over the 16 lanes that share a row-pair (offsets 1..8)
    float s0 = (a00 + a01) + (a02 + a03);
    float q0 = (a00 * a00 + a01 * a01) + (a02 * a02 + a03 * a03);
    float s1 = (a10 + a11) + (a12 + a13);
    float q1 = (a10 * a10 + a11 * a11) + (a12 * a12 + a13 * a13);
#pragma unroll
    for (int off = 8; off; off >>= 1) {
        s0 += __shfl_xor_sync(0xffffffffu, s0, off);
        q0 += __shfl_xor_sync(0xffffffffu, q0, off);
        s1 += __shfl_xor_sync(0xffffffffu, s1, off);
        q1 += __shfl_xor_sync(0xffffffffu, q1, off);
    }
    float mu0 = s0 * (1.0f / 64.0f);
    float var0 = q0 * (1.0f / 64.0f) - mu0 * mu0;
    float ri0 = rsqrtf(var0 + 1e-5f);
    float mu1 = s1 * (1.0f / 64.0f);
    float var1 = q1 * (1.0f / 64.0f) - mu1 * mu1;
    float ri1 = rsqrtf(var1 + 1e-5f);

    float w0 = sw[e0], w1 = sw[e0 + 1], w2 = sw[e0 + 2], w3 = sw[e0 + 3];
    float g0 = sbeta[e0], g1 = sbeta[e0 + 1], g2 = sbeta[e0 + 2], g3 = sbeta[e0 + 3];

    *(float4*)&sy[r0][e0] = make_float4((a00 - mu0) * ri0 * w0 + g0,
                                        (a01 - mu0) * ri0 * w1 + g1,
                                        (a02 - mu0) * ri0 * w2 + g2,
                                        (a03 - mu0) * ri0 * w3 + g3);
    *(float4*)&sy[r0 + 1][e0] = make_float4((a10 - mu1) * ri1 * w0 + g0,
                                            (a11 - mu1) * ri1 * w1 + g1,
                                            (a12 - mu1) * ri1 * w2 + g2,
                                            (a13 - mu1) * ri1 * w3 + g3);
    __syncthreads();

    // write h = 0 slice only (coalesced STG.128)
    const float4* sy4 = (const float4*)sy;
    float4* dst = (float4*)out + n * 4096 + lc * 512 + tid;
    dst[0] = sy4[tid];
    dst[256] = sy4[tid + 256];
}

// ---------------------------------------------------------------------------
// K4: broadcast h=0 slice (4 MB) to h = 1..63 (252 MB of streaming writes).
// R6-proven structure: 256 blocks, 16 KB segment in 4 registers per thread,
// 63 independent strided STG.128 stores per register, __stcs streaming hint.
// ---------------------------------------------------------------------------
__global__ void __launch_bounds__(256) k_bcast(float* __restrict__ out) {
    const int tid = threadIdx.x;
    const size_t segOff4 = (size_t)blockIdx.x * 1024;  // float4 units (16KB/block)
    const float4* src = (const float4*)out + segOff4;
    float4 v0 = src[tid];
    float4 v1 = src[tid + 256];
    float4 v2 = src[tid + 512];
    float4 v3 = src[tid + 768];
    float4* dst = (float4*)out + segOff4 + tid;
    const size_t hstride4 = (size_t)NB * LQ * EE / 4;  // 262144 float4 = 4 MB
#pragma unroll 7
    for (int h = 1; h < HH; h++) {
        float4* p = dst + (size_t)h * hstride4;
        __stcs(p, v0);
        __stcs(p + 256, v1);
        __stcs(p + 512, v2);
        __stcs(p + 768, v3);
    }
}

// ---------------------------------------------------------------------------
extern "C" void kernel_launch(void* const* d_in, const int* in_sizes, int n_in,
                              void* d_out, int out_size) {
    const float* values = (const float*)d_in[0];
    const float* keys   = (const float*)d_in[1];
    const float* query  = (const float*)d_in[2];
    const float* W      = (const float*)d_in[3];
    const float* b      = (const float*)d_in[4];
    const float* lnw    = (const float*)d_in[5];
    const float* lnb    = (const float*)d_in[6];
    float* out = (float*)d_out;

    k_front<<<384, 256>>>(values, query, keys);
    k_compute<<<512, 256>>>(W, b, lnw, lnb, out);
    k_bcast<<<256, 256>>>(out);
}

// round 10
// speedup vs baseline: 1.0813x; 1.0813x over previous
#include <cuda_runtime.h>

#define NB 64
#define LQ 256
#define EE 64
#define HH 64

// Scratch (static __device__ — no allocations allowed)
__device__ float g_vt[NB * LQ * EE];    // vt[n][l][k] = values[k][l][n]   (4 MB)
__device__ float g_attn[NB * EE * EE];  // attn[n][a][b]                   (1 MB)
__device__ float g_M[NB * EE * EE];     // M[n][e][k] = (W @ A_n)[e][k]    (1 MB)

// ---------------------------------------------------------------------------
// K_front: merged launch.
//   blocks [0,128):   energy Q·K^T + softmax -> g_attn  (n, half) [long pole]
//   blocks [128,384): transpose values[k][l][n] -> vt[n][l][k]  (one per l)
// Attn phase uses register prefetch: next chunk's Q/K LDGs issue before the
// current chunk's 32-iter compute, hiding ~600cyc LDG latency per chunk.
// ---------------------------------------------------------------------------
__global__ void __launch_bounds__(256) k_front(const float* __restrict__ values,
                                               const float* __restrict__ query,
                                               const float* __restrict__ keys) {
    __shared__ float sh[5248];           // aliased pool (max of both phases)
    const int tid = threadIdx.x;

    if (blockIdx.x >= 128) {
        // ---- transpose phase ----
        float (*tile)[65] = (float(*)[65])sh;
        const int l = blockIdx.x - 128;
#pragma unroll
        for (int i = 0; i < 4; i++) {
            int f = i * 256 + tid;          // float4 index 0..1023
            int k = f >> 4;                 // 0..63
            int n4 = f & 15;                // 0..15
            float4 v = *(const float4*)(values + ((k * LQ + l) * EE) + n4 * 4);
            tile[k][n4 * 4 + 0] = v.x;
            tile[k][n4 * 4 + 1] = v.y;
            tile[k][n4 * 4 + 2] = v.z;
            tile[k][n4 * 4 + 3] = v.w;
        }
        __syncthreads();
#pragma unroll
        for (int i = 0; i < 4; i++) {
            int f = i * 256 + tid;
            int nn = f >> 4;
            int k4 = f & 15;
            float4 v = make_float4(tile[k4 * 4 + 0][nn], tile[k4 * 4 + 1][nn],
                                   tile[k4 * 4 + 2][nn], tile[k4 * 4 + 3][nn]);
            *(float4*)(g_vt + ((nn * LQ + l) * EE) + k4 * 4) = v;
        }
        return;
    }

    // ---- attention phase ----
    const int n = blockIdx.x >> 1;
    const int half = blockIdx.x & 1;
    float (*sQ)[32] = (float(*)[32])sh;            // [l'][a_local]  1024
    float (*sK)[64] = (float(*)[64])(sh + 1024);   // [l'][b]        2048
    float (*sE)[68] = (float(*)[68])(sh + 3072);   // energy         2176
    const int a0 = (tid >> 4) * 2;  // 0..30 step 2
    const int b0 = (tid & 15) * 4;  // 0..60 step 4

    // per-thread load slots
    const int qlp = tid >> 3;        // 0..31 (Q row)
    const int qc = (tid & 7) * 4;    // 0..28 (Q col*4)
    const int klp0 = tid >> 4;       // 0..15 (K rows: tid and tid+256)
    const int kc = (tid & 15) * 4;   // 0..60

    float a00 = 0.f, a01 = 0.f, a02 = 0.f, a03 = 0.f;
    float a10 = 0.f, a11 = 0.f, a12 = 0.f, a13 = 0.f;

    // prefetch chunk 0
    float4 qreg = *(const float4*)(query + ((n * LQ + qlp) * EE) + half * 32 + qc);
    float4 kreg0 = *(const float4*)(keys + ((n * LQ + klp0) * EE) + kc);
    float4 kreg1 = *(const float4*)(keys + ((n * LQ + 16 + klp0) * EE) + kc);

    for (int c = 0; c < 8; c++) {
        *(float4*)&sQ[qlp][qc] = qreg;
        *(float4*)&sK[klp0][kc] = kreg0;
        *(float4*)&sK[16 + klp0][kc] = kreg1;
        __syncthreads();

        if (c < 7) {
            const int l0 = (c + 1) * 32;
            qreg = *(const float4*)(query + ((n * LQ + l0 + qlp) * EE) + half * 32 + qc);
            kreg0 = *(const float4*)(keys + ((n * LQ + l0 + klp0) * EE) + kc);
            kreg1 = *(const float4*)(keys + ((n * LQ + l0 + 16 + klp0) * EE) + kc);
        }

#pragma unroll
        for (int lp = 0; lp < 32; lp++) {
            float2 qv = *(const float2*)&sQ[lp][a0];
            float4 kv = *(const float4*)&sK[lp][b0];
            a00 += qv.x * kv.x; a01 += qv.x * kv.y; a02 += qv.x * kv.z; a03 += qv.x * kv.w;
            a10 += qv.y * kv.x; a11 += qv.y * kv.y; a12 += qv.y * kv.z; a13 += qv.y * kv.w;
        }
        __syncthreads();
    }
    *(float4*)&sE[a0][b0]     = make_float4(a00, a01, a02, a03);
    *(float4*)&sE[a0 + 1][b0] = make_float4(a10, a11, a12, a13);
    __syncthreads();

    // softmax: 8 warps x 4 rows each (32 rows in this half); hd=1 so no scale
    const int w = tid >> 5, lane = tid & 31;
#pragma unroll
    for (int r = 0; r < 4; r++) {
        int row = w * 4 + r;
        float v0 = sE[row][lane];
        float v1 = sE[row][lane + 32];
        float m = fmaxf(v0, v1);
#pragma unroll
        for (int off = 16; off; off >>= 1) m = fmaxf(m, __shfl_xor_sync(0xffffffffu, m, off));
        float e0 = __expf(v0 - m);
        float e1 = __expf(v1 - m);
        float s = e0 + e1;
#pragma unroll
        for (int off = 16; off; off >>= 1) s += __shfl_xor_sync(0xffffffffu, s, off);
        float inv = 1.0f / s;
        float* dst = g_attn + (n * EE + half * 32 + row) * EE;
        dst[lane] = e0 * inv;
        dst[lane + 32] = e1 * inv;
    }
}

// ---------------------------------------------------------------------------
// K2: M_n[e][k] = sum_e' W[e][e'] * attn[n][e'][k]   (fold fc into attn)
// grid: 64 blocks (one per n)
// ---------------------------------------------------------------------------
__global__ void __launch_bounds__(256) k_M(const float* __restrict__ W) {
    const int n = blockIdx.x;
    __shared__ float sWt[64][68];  // sWt[e'][e] = W[e][e']
    __shared__ float sA[64][68];   // sA[e'][k]
    const int tid = threadIdx.x;
#pragma unroll
    for (int i = 0; i < 16; i++) {
        int idx = i * 256 + tid;
        int r = idx >> 6, c = idx & 63;
        sWt[c][r] = W[idx];                       // transpose W on the fly
        sA[r][c] = g_attn[n * 4096 + idx];
    }
    __syncthreads();
    const int e0 = (tid >> 4) * 4;
    const int k0 = (tid & 15) * 4;
    float acc[4][4] = {};
#pragma unroll
    for (int ep = 0; ep < 64; ep++) {
        float4 wv = *(const float4*)&sWt[ep][e0];
        float4 av = *(const float4*)&sA[ep][k0];
        acc[0][0] += wv.x * av.x; acc[0][1] += wv.x * av.y; acc[0][2] += wv.x * av.z; acc[0][3] += wv.x * av.w;
        acc[1][0] += wv.y * av.x; acc[1][1] += wv.y * av.y; acc[1][2] += wv.y * av.z; acc[1][3] += wv.y * av.w;
        acc[2][0] += wv.z * av.x; acc[2][1] += wv.z * av.y; acc[2][2] += wv.z * av.z; acc[2][3] += wv.z * av.w;
        acc[3][0] += wv.w * av.x; acc[3][1] += wv.w * av.y; acc[3][2] += wv.w * av.z; acc[3][3] += wv.w * av.w;
    }
#pragma unroll
    for (int i = 0; i < 4; i++) {
        *(float4*)(g_M + ((n * 64 + e0 + i) * 64) + k0) =
            make_float4(acc[i][0], acc[i][1], acc[i][2], acc[i][3]);
    }
}

// ---------------------------------------------------------------------------
// K3: tiled GEMV + LayerNorm; writes ONLY the h=0 slice (4 MB).
// grid: 512 blocks = (n, 32-l chunk); 256 threads = (16 l-pairs) x (16 e-quads)
// ---------------------------------------------------------------------------
__global__ void __launch_bounds__(256) k_compute(const float* __restrict__ bias,
                                                 const float* __restrict__ lnw,
                                                 const float* __restrict__ lnb,
                                                 float* __restrict__ out) {
    const int n = blockIdx.x >> 3;
    const int lc = blockIdx.x & 7;
    const int tid = threadIdx.x;

    __shared__ float sMt[64][68];   // sMt[k][e] = M_n[e][k]
    __shared__ float sv[32][68];    // sv[l'][k]
    __shared__ float sy[32][64];    // normalized output tile
    __shared__ float sb[64], sw[64], sbeta[64];

    if (tid < 64) {
        sb[tid] = bias[tid];
        sw[tid] = lnw[tid];
        sbeta[tid] = lnb[tid];
    }

    // Load + transpose M_n (64x64) into sMt[k][e]
    const float* Mn = g_M + n * 4096;
#pragma unroll
    for (int i = 0; i < 16; i++) {
        int idx = i * 256 + tid;
        int e = idx >> 6, k = idx & 63;
        sMt[k][e] = Mn[idx];
    }
    // Load vt tile (32 x 64), coalesced
    const int lbase = lc * 32;
    const float* vtn = g_vt + (n * LQ + lbase) * EE;
#pragma unroll
    for (int i = 0; i < 8; i++) {
        int idx = i * 256 + tid;
        sv[idx >> 6][idx & 63] = vtn[idx];
    }
    __syncthreads();

    // Micro-tile: 2 l-rows x 4 e-cols per thread
    const int r0 = (tid >> 4) * 2;   // 0..30
    const int e0 = (tid & 15) * 4;   // 0..60

    float a00 = 0.f, a01 = 0.f, a02 = 0.f, a03 = 0.f;
    float a10 = 0.f, a11 = 0.f, a12 = 0.f, a13 = 0.f;
#pragma unroll
    for (int k = 0; k < 64; k++) {
        float v0 = sv[r0][k];
        float v1 = sv[r0 + 1][k];
        float4 m = *(const float4*)&sMt[k][e0];
        a00 += v0 * m.x; a01 += v0 * m.y; a02 += v0 * m.z; a03 += v0 * m.w;
        a10 += v1 * m.x; a11 += v1 * m.y; a12 += v1 * m.z; a13 += v1 * m.w;
    }
    // add fc bias before LN
    float b0v = sb[e0], b1v = sb[e0 + 1], b2v = sb[e0 + 2], b3v = sb[e0 + 3];
    a00 += b0v; a01 += b1v; a02 += b2v; a03 += b3v;
    a10 += b0v; a11 += b1v; a12 += b2v; a13 += b3v;

    // LN stats: reduce over the 16 lanes that share a row-pair (offsets 1..8)
    float s0 = (a00 + a01) + (a02 + a03);
    float q0 = (a00 * a00 + a01 * a01) + (a02 * a02 + a03 * a03);
    float s1 = (a10 + a11) + (a12 + a13);
    float q1 = (a10 * a10 + a11 * a11) + (a12 * a12 + a13 * a13);
#pragma unroll
    for (int off = 8; off; off >>= 1) {
        s0 += __shfl_xor_sync(0xffffffffu, s0, off);
        q0 += __shfl_xor_sync(0xffffffffu, q0, off);
        s1 += __shfl_xor_sync(0xffffffffu, s1, off);
        q1 += __shfl_xor_sync(0xffffffffu, q1, off);
    }
    float mu0 = s0 * (1.0f / 64.0f);
    float var0 = q0 * (1.0f / 64.0f) - mu0 * mu0;
    float ri0 = rsqrtf(var0 + 1e-5f);
    float mu1 = s1 * (1.0f / 64.0f);
    float var1 = q1 * (1.0f / 64.0f) - mu1 * mu1;
    float ri1 = rsqrtf(var1 + 1e-5f);

    float w0 = sw[e0], w1 = sw[e0 + 1], w2 = sw[e0 + 2], w3 = sw[e0 + 3];
    float g0 = sbeta[e0], g1 = sbeta[e0 + 1], g2 = sbeta[e0 + 2], g3 = sbeta[e0 + 3];

    *(float4*)&sy[r0][e0] = make_float4((a00 - mu0) * ri0 * w0 + g0,
                                        (a01 - mu0) * ri0 * w1 + g1,
                                        (a02 - mu0) * ri0 * w2 + g2,
                                        (a03 - mu0) * ri0 * w3 + g3);
    *(float4*)&sy[r0 + 1][e0] = make_float4((a10 - mu1) * ri1 * w0 + g0,
                                            (a11 - mu1) * ri1 * w1 + g1,
                                            (a12 - mu1) * ri1 * w2 + g2,
                                            (a13 - mu1) * ri1 * w3 + g3);
    __syncthreads();

    // write h = 0 slice only (coalesced STG.128)
    const float4* sy4 = (const float4*)sy;
    float4* dst = (float4*)out + n * 4096 + lc * 512 + tid;
    dst[0] = sy4[tid];
    dst[256] = sy4[tid + 256];
}

// ---------------------------------------------------------------------------
// K4: broadcast h=0 slice (4 MB) to h = 1..63 (252 MB of streaming writes).
// R6-proven structure: 256 blocks, 16 KB segment in 4 registers per thread,
// 63 independent strided STG.128 stores per register, __stcs streaming hint.
// ---------------------------------------------------------------------------
__global__ void __launch_bounds__(256) k_bcast(float* __restrict__ out) {
    const int tid = threadIdx.x;
    const size_t segOff4 = (size_t)blockIdx.x * 1024;  // float4 units (16KB/block)
    const float4* src = (const float4*)out + segOff4;
    float4 v0 = src[tid];
    float4 v1 = src[tid + 256];
    float4 v2 = src[tid + 512];
    float4 v3 = src[tid + 768];
    float4* dst = (float4*)out + segOff4 + tid;
    const size_t hstride4 = (size_t)NB * LQ * EE / 4;  // 262144 float4 = 4 MB
#pragma unroll 7
    for (int h = 1; h < HH; h++) {
        float4* p = dst + (size_t)h * hstride4;
        __stcs(p, v0);
        __stcs(p + 256, v1);
        __stcs(p + 512, v2);
        __stcs(p + 768, v3);
    }
}

// ---------------------------------------------------------------------------
extern "C" void kernel_launch(void* const* d_in, const int* in_sizes, int n_in,
                              void* d_out, int out_size) {
    const float* values = (const float*)d_in[0];
    const float* keys   = (const float*)d_in[1];
    const float* query  = (const float*)d_in[2];
    const float* W      = (const float*)d_in[3];
    const float* b      = (const float*)d_in[4];
    const float* lnw    = (const float*)d_in[5];
    const float* lnb    = (const float*)d_in[6];
    float* out = (float*)d_out;

    k_front<<<384, 256>>>(values, query, keys);
    k_M<<<64, 256>>>(W);
    k_compute<<<512, 256>>>(b, lnw, lnb, out);
    k_bcast<<<256, 256>>>(out);
}